// round 1
// baseline (speedup 1.0000x reference)
#include <cuda_runtime.h>

// ---------------- problem dims ----------------
#define DIM_B 32
#define DIM_P 8
#define DIM_K 8
#define DIM_D 768
#define DIM_G 20000
#define TOPK_N 200

constexpr int BP  = DIM_B * DIM_P;   // 256
constexpr int KD  = DIM_K * DIM_D;   // 6144
constexpr int MQ  = BP * DIM_K;      // 2048 (rows of Q / Qw / A)
constexpr float SCALE = 0.036084391824351615f; // 768^-0.5

// ---------------- scratch (device globals; no alloc) ----------------
__device__ float g_w[DIM_K];
__device__ float g_Qw[MQ * DIM_D];      // 2048 x 768 (= 256 x 6144)
__device__ float g_A [MQ * DIM_D];      // 2048 x 768 (= 256 x 6144)
__device__ float g_rowbias[BP];

// ---------------- f32x2 packed-math helpers ----------------
__device__ __forceinline__ unsigned long long pk2(float x, float y) {
    unsigned long long r;
    asm("mov.b64 %0, {%1,%2};" : "=l"(r) : "f"(x), "f"(y));
    return r;
}
__device__ __forceinline__ void fma2(unsigned long long& d,
                                     unsigned long long a,
                                     unsigned long long b) {
    asm("fma.rn.f32x2 %0, %1, %2, %0;" : "+l"(d) : "l"(a), "l"(b));
}
__device__ __forceinline__ float2 upk2(unsigned long long v) {
    float2 r;
    asm("mov.b64 {%0,%1}, %2;" : "=f"(r.x), "=f"(r.y) : "l"(v));
    return r;
}
__device__ __forceinline__ float4 ld4g(const float* p, bool v) {
    if (v) return *reinterpret_cast<const float4*>(p);
    return make_float4(0.f, 0.f, 0.f, 0.f);
}

// ---------------- generic 128x128x8 fp32 GEMM ----------------
// LAYB: 0 = TN (B is N x Kd row-major, contraction contiguous -> C[m][n]=A[m,:]·B[n,:])
//       1 = NN (B is Kd x N row-major -> C[m][n]=Σ_k A[m][k]*B[k][n]); full tiles assumed
// EPI : 0 = none; 1 = C=(acc+bias[n])*(SCALE*g_w[m&7]); 2 = C=acc+bias[m], guard n<N
constexpr int BM = 128, BN = 128, BKT = 8;

template<int LAYB, int EPI>
__global__ void __launch_bounds__(256, 2)
gemm_f32(const float* __restrict__ A, const float* __restrict__ B,
         float* __restrict__ C, int M, int N, int Kd,
         const float* __restrict__ bias)
{
    __shared__ __align__(16) float As[2][BKT][BM];
    __shared__ __align__(16) float Bs[2][BKT][BN];

    const int tid = threadIdx.x;
    const int tx = tid & 15, ty = tid >> 4;
    const int m0 = blockIdx.y * BM;
    const int n0 = blockIdx.x * BN;

    // A tile loader: 128(m) x 8(k), 4 floats/thread
    const int a_m = tid >> 1, a_k = (tid & 1) * 4;
    const float* Ag = A + (size_t)(m0 + a_m) * Kd + a_k;

    // B tile loader
    int b_r, b_c; bool bval; const float* Bg;
    if (LAYB == 0) {
        b_r = tid >> 1; b_c = (tid & 1) * 4;          // 128(n) x 8(k)
        bval = (n0 + b_r) < N;
        Bg = B + (size_t)(n0 + b_r) * Kd + b_c;
    } else {
        b_r = tid >> 5; b_c = (tid & 31) * 4;         // 8(k) x 128(n)
        bval = true;
        Bg = B + (size_t)b_r * N + (n0 + b_c);
    }

    // prologue: load tile 0
    float4 ar = ld4g(Ag, true);
    float4 br = (LAYB == 0) ? ld4g(Bg, bval) : ld4g(Bg, true);

    As[0][a_k + 0][a_m] = ar.x; As[0][a_k + 1][a_m] = ar.y;
    As[0][a_k + 2][a_m] = ar.z; As[0][a_k + 3][a_m] = ar.w;
    if (LAYB == 0) {
        Bs[0][b_c + 0][b_r] = br.x; Bs[0][b_c + 1][b_r] = br.y;
        Bs[0][b_c + 2][b_r] = br.z; Bs[0][b_c + 3][b_r] = br.w;
    } else {
        *reinterpret_cast<float4*>(&Bs[0][b_r][b_c]) = br;
    }
    __syncthreads();

    unsigned long long acc[8][4];
#pragma unroll
    for (int i = 0; i < 8; ++i)
#pragma unroll
        for (int j = 0; j < 4; ++j) acc[i][j] = 0ull;

    const int nt = Kd / BKT;
    for (int t = 0; t < nt; ++t) {
        const int cur = t & 1;
        const bool hn = (t + 1) < nt;
        if (hn) {
            ar = ld4g(Ag + (t + 1) * BKT, true);
            if (LAYB == 0) br = ld4g(Bg + (t + 1) * BKT, bval);
            else           br = ld4g(Bg + (size_t)(t + 1) * BKT * N, true);
        }
#pragma unroll
        for (int kk = 0; kk < BKT; ++kk) {
            const float4 av0 = *reinterpret_cast<const float4*>(&As[cur][kk][ty * 8]);
            const float4 av1 = *reinterpret_cast<const float4*>(&As[cur][kk][ty * 8 + 4]);
            const ulonglong2 bv0 = *reinterpret_cast<const ulonglong2*>(&Bs[cur][kk][tx * 8]);
            const ulonglong2 bv1 = *reinterpret_cast<const ulonglong2*>(&Bs[cur][kk][tx * 8 + 4]);
            const float a8[8] = {av0.x, av0.y, av0.z, av0.w, av1.x, av1.y, av1.z, av1.w};
#pragma unroll
            for (int i = 0; i < 8; ++i) {
                const unsigned long long aa = pk2(a8[i], a8[i]);
                fma2(acc[i][0], aa, bv0.x);
                fma2(acc[i][1], aa, bv0.y);
                fma2(acc[i][2], aa, bv1.x);
                fma2(acc[i][3], aa, bv1.y);
            }
        }
        if (hn) {
            const int nb = (t + 1) & 1;
            As[nb][a_k + 0][a_m] = ar.x; As[nb][a_k + 1][a_m] = ar.y;
            As[nb][a_k + 2][a_m] = ar.z; As[nb][a_k + 3][a_m] = ar.w;
            if (LAYB == 0) {
                Bs[nb][b_c + 0][b_r] = br.x; Bs[nb][b_c + 1][b_r] = br.y;
                Bs[nb][b_c + 2][b_r] = br.z; Bs[nb][b_c + 3][b_r] = br.w;
            } else {
                *reinterpret_cast<float4*>(&Bs[nb][b_r][b_c]) = br;
            }
        }
        __syncthreads();
    }

    // epilogue
#pragma unroll
    for (int i = 0; i < 8; ++i) {
        const int m = m0 + ty * 8 + i;
        float rs = 1.f, badd = 0.f;
        if (EPI == 1) rs = SCALE * g_w[m & 7];
        if (EPI == 2) badd = bias[m];
#pragma unroll
        for (int j = 0; j < 4; ++j) {
            float2 v = upk2(acc[i][j]);
            const int n = n0 + tx * 8 + j * 2;
            if (EPI == 1) {
                v.x = (v.x + bias[n])     * rs;
                v.y = (v.y + bias[n + 1]) * rs;
            } else {
                v.x += badd; v.y += badd;
            }
            if (n < N)  // N is even; n even -> n+1 < N too
                *reinterpret_cast<float2*>(&C[(size_t)m * N + n]) = v;
        }
    }
}

// ---------------- small kernels ----------------
__global__ void k_prep(const float* __restrict__ fw, float* __restrict__ tail, int wt) {
    if (threadIdx.x == 0) {
        float mx = fw[0];
        for (int k = 1; k < DIM_K; ++k) mx = fmaxf(mx, fw[k]);
        float e[DIM_K], s = 0.f;
        for (int k = 0; k < DIM_K; ++k) { e[k] = expf(fw[k] - mx); s += e[k]; }
        for (int k = 0; k < DIM_K; ++k) {
            const float w = e[k] / s;
            g_w[k] = w;
            if (wt) tail[k] = w;
        }
    }
}

// rowbias[bp] = Σ_k log(max(conf,1e-6))·w[k]  +  Σ_k Qw[bp,k,:]·bk
__global__ void k_rowbias(const float* __restrict__ conf, const float* __restrict__ bk) {
    const int bp = blockIdx.x, tid = threadIdx.x;
    __shared__ float red[256];
    const float* q = g_Qw + (size_t)bp * KD;
    float s = 0.f;
    for (int e = tid; e < DIM_D; e += 256) {
        const float b = bk[e];
#pragma unroll
        for (int k = 0; k < DIM_K; ++k) s += q[k * DIM_D + e] * b;
    }
    red[tid] = s; __syncthreads();
    for (int off = 128; off > 0; off >>= 1) {
        if (tid < off) red[tid] += red[tid + off];
        __syncthreads();
    }
    if (tid == 0) {
        float cb = 0.f;
        for (int k = 0; k < DIM_K; ++k)
            cb += logf(fmaxf(conf[bp * DIM_K + k], 1e-6f)) * g_w[k];
        g_rowbias[bp] = red[0] + cb;
    }
}

// exact top-200 per row via 32-bit binary search on order-preserving keys;
// keys live in registers (40/thread), then mask in place.
__global__ void __launch_bounds__(512) k_topk(float* __restrict__ io) {
    const int row = blockIdx.x, tid = threadIdx.x;
    float* p = io + (size_t)row * DIM_G;

    unsigned keys[40];
#pragma unroll
    for (int it = 0; it < 40; ++it) {
        const int j = tid + it * 512;
        unsigned key = 0u;                       // below every real key
        if (j < DIM_G) {
            const unsigned u = __float_as_uint(p[j]);
            key = (u & 0x80000000u) ? ~u : (u | 0x80000000u);
        }
        keys[it] = key;
    }

    __shared__ int s_cnt;
    unsigned prefix = 0u;
    for (int b = 31; b >= 0; --b) {
        const unsigned cand = prefix | (1u << b);
        if (tid == 0) s_cnt = 0;
        __syncthreads();
        int c = 0;
#pragma unroll
        for (int it = 0; it < 40; ++it) c += (keys[it] >= cand);
        c = __reduce_add_sync(0xFFFFFFFFu, c);
        if ((tid & 31) == 0) atomicAdd(&s_cnt, c);
        __syncthreads();
        if (s_cnt >= TOPK_N) prefix = cand;      // keep invariant count(>=prefix) >= K
        __syncthreads();
    }
    // prefix == 200th-largest key exactly (distinct keys); keep >= prefix
#pragma unroll
    for (int it = 0; it < 40; ++it) {
        const int j = tid + it * 512;
        if (j < DIM_G && keys[it] < prefix) p[j] = 0.0f;
    }
}

// ---------------- launch ----------------
extern "C" void kernel_launch(void* const* d_in, const int* in_sizes, int n_in,
                              void* d_out, int out_size) {
    const float* cQ   = (const float*)d_in[0];  // (B,P,K,D)
    const float* GF   = (const float*)d_in[1];  // (G,K,D)
    const float* conf = (const float*)d_in[2];  // (B,P,K)
    const float* Wq   = (const float*)d_in[3];  // (D,D)
    const float* bq   = (const float*)d_in[4];  // (D)
    const float* Wk   = (const float*)d_in[5];  // (D,D)
    const float* bk   = (const float*)d_in[6];  // (D)
    const float* fw   = (const float*)d_in[7];  // (K)
    float* out = (float*)d_out;

    float *pQw = nullptr, *pA = nullptr, *pRB = nullptr;
    cudaGetSymbolAddress((void**)&pQw, g_Qw);
    cudaGetSymbolAddress((void**)&pA,  g_A);
    cudaGetSymbolAddress((void**)&pRB, g_rowbias);

    const int BPG = BP * DIM_G;
    const int wt = (out_size >= BPG + DIM_K) ? 1 : 0;

    // 1) softmax(facet_weights) -> g_w (+ output tail)
    k_prep<<<1, 32>>>(fw, out + BPG, wt);

    // 2) Qw = (cQ @ Wq^T + bq) * (SCALE * w[k])   [TN: contraction contiguous in both]
    gemm_f32<0, 1><<<dim3(DIM_D / BN, MQ / BM), 256>>>(cQ, Wq, pQw, MQ, DIM_D, DIM_D, bq);

    // 3) rowbias[bp] = conf_bias + Qw·bk
    k_rowbias<<<BP, 256>>>(conf, bk);

    // 4) A = Qw @ Wk                              [NN]
    gemm_f32<1, 0><<<dim3(DIM_D / BN, MQ / BM), 256>>>(pQw, Wk, pA, MQ, DIM_D, DIM_D, nullptr);

    // 5) impact = A_flat(256x6144) @ GF_flat^T(20000x6144) + rowbias[m]   [TN]
    gemm_f32<0, 2><<<dim3((DIM_G + BN - 1) / BN, BP / BM), 256>>>(pA, GF, out, BP, DIM_G, KD, pRB);

    // 6) exact top-200 mask, in place
    k_topk<<<BP, 512>>>(out);
}